// round 11
// baseline (speedup 1.0000x reference)
#include <cuda_runtime.h>
#include <cuda_fp16.h>
#include <math.h>
#include <stdint.h>

#define NNODES 8192
#define HIDDIM 512
#define KTOP   16
#define TKK    17   // top_k + 1

// ---------------- scratch (static __device__ — no allocations allowed) ----------
__device__ float  g_h0[NNODES * HIDDIM];
__device__ float  g_h1[NNODES * HIDDIM];
__device__ float  g_f [NNODES * HIDDIM];
__device__ float  g_fused [NNODES * HIDDIM];
__device__ __half g_nh[NNODES * HIDDIM];   // hi half of normed
__device__ __half g_nl[NNODES * HIDDIM];   // lo half of normed
__device__ float  g_rowmean[NNODES];
__device__ float  g_sim[(size_t)NNODES * NNODES];
__device__ int    g_nbrs[NNODES * KTOP];
__device__ float  g_w[NNODES];
__device__ int    g_keep[NNODES];

// ---------------- packed f32x2 helpers (fp32 FMA path for MLP GEMMs) ------------
__device__ __forceinline__ unsigned long long dup2(float x) {
    unsigned long long r;
    asm("mov.b64 %0, {%1, %1};" : "=l"(r) : "f"(x));
    return r;
}
__device__ __forceinline__ void fma2(unsigned long long &c,
                                     unsigned long long a,
                                     unsigned long long b) {
    asm("fma.rn.f32x2 %0, %1, %2, %3;" : "=l"(c) : "l"(a), "l"(b), "l"(c));
}
union U2 { unsigned long long u; float2 f; };

// ---------------- HMMA + cp.async + ldmatrix helpers (sm_80+, sm_100-safe) ------
__device__ __forceinline__ void hmma(float* c,
                                     const uint32_t* a,
                                     uint32_t b0, uint32_t b1) {
    asm volatile(
        "mma.sync.aligned.m16n8k16.row.col.f32.f16.f16.f32 "
        "{%0,%1,%2,%3}, {%4,%5,%6,%7}, {%8,%9}, {%0,%1,%2,%3};"
        : "+f"(c[0]), "+f"(c[1]), "+f"(c[2]), "+f"(c[3])
        : "r"(a[0]), "r"(a[1]), "r"(a[2]), "r"(a[3]), "r"(b0), "r"(b1));
}
// fp16-accumulate variant (2 output regs = 4 halves) — used for the small
// hi*lo / lo*hi correction terms only.
__device__ __forceinline__ void hmma16(uint32_t* c,
                                       const uint32_t* a,
                                       uint32_t b0, uint32_t b1) {
    asm volatile(
        "mma.sync.aligned.m16n8k16.row.col.f16.f16.f16.f16 "
        "{%0,%1}, {%2,%3,%4,%5}, {%6,%7}, {%0,%1};"
        : "+r"(c[0]), "+r"(c[1])
        : "r"(a[0]), "r"(a[1]), "r"(a[2]), "r"(a[3]), "r"(b0), "r"(b1));
}
__device__ __forceinline__ void ldmx4(uint32_t* d, uint32_t addr) {
    asm volatile(
        "ldmatrix.sync.aligned.m8n8.x4.shared.b16 {%0,%1,%2,%3}, [%4];"
        : "=r"(d[0]), "=r"(d[1]), "=r"(d[2]), "=r"(d[3]) : "r"(addr));
}
__device__ __forceinline__ uint32_t smem_u32(const void* p) {
    uint32_t a;
    asm("{ .reg .u64 t; cvta.to.shared.u64 t, %1; cvt.u32.u64 %0, t; }"
        : "=r"(a) : "l"(p));
    return a;
}
__device__ __forceinline__ void cpasync16(uint32_t dst, const void* src) {
    asm volatile("cp.async.cg.shared.global [%0], [%1], 16;"
                 :: "r"(dst), "l"(src));
}
#define CP_COMMIT() asm volatile("cp.async.commit_group;" ::: "memory")
#define CP_WAIT0()  asm volatile("cp.async.wait_group 0;" ::: "memory")

// =================================================================================
// GEMM NN (fp32, f32x2 FMA path) — R9-passing version, unchanged.
// =================================================================================
template<int RELU, int AMODE, int ACCUM>
__global__ void __launch_bounds__(256, 2) gemm_nn(
    const float* __restrict__ A, const float* __restrict__ B,
    const float* __restrict__ bias, const float* __restrict__ attn,
    float* __restrict__ C, int M, int N, int K)
{
    __shared__ __align__(16) float As[2][8][128];
    __shared__ __align__(16) float Bs[2][8][128];

    const int tid = threadIdx.x;
    const int m0 = blockIdx.y * 128;
    const int n0 = blockIdx.x * 128;

    const int a_row = tid >> 1, a_col = (tid & 1) * 4;
    const int b_row = tid >> 5, b_col = (tid & 31) * 4;
    const float* Ap = A + (size_t)(m0 + a_row) * K + a_col;
    const float* Bp = B + (size_t)b_row * N + n0 + b_col;

    {
        float4 a4 = *(const float4*)Ap;
        float4 b4 = *(const float4*)Bp;
        As[0][a_col + 0][a_row] = a4.x; As[0][a_col + 1][a_row] = a4.y;
        As[0][a_col + 2][a_row] = a4.z; As[0][a_col + 3][a_row] = a4.w;
        *(float4*)&Bs[0][b_row][b_col] = b4;
    }
    __syncthreads();

    const int ry = tid >> 4;
    const int cx = tid & 15;

    unsigned long long acc[8][4];
#pragma unroll
    for (int i = 0; i < 8; ++i)
#pragma unroll
        for (int p = 0; p < 4; ++p) acc[i][p] = 0ull;

    const int nt = K >> 3;
    for (int t = 0; t < nt; ++t) {
        const int cur = t & 1;
        float4 na, nb;
        if (t + 1 < nt) {
            na = *(const float4*)(Ap + (t + 1) * 8);
            nb = *(const float4*)(Bp + (size_t)(t + 1) * 8 * N);
        }
#pragma unroll
        for (int k = 0; k < 8; ++k) {
            float4 aA = *(const float4*)&As[cur][k][ry * 4];
            float4 aB = *(const float4*)&As[cur][k][64 + ry * 4];
            const unsigned long long* bp0 =
                (const unsigned long long*)&Bs[cur][k][cx * 4];
            const unsigned long long* bp1 =
                (const unsigned long long*)&Bs[cur][k][64 + cx * 4];
            unsigned long long b0 = bp0[0], b1 = bp0[1];
            unsigned long long b2 = bp1[0], b3 = bp1[1];
            unsigned long long da[8] = {
                dup2(aA.x), dup2(aA.y), dup2(aA.z), dup2(aA.w),
                dup2(aB.x), dup2(aB.y), dup2(aB.z), dup2(aB.w)
            };
#pragma unroll
            for (int i = 0; i < 8; ++i) {
                fma2(acc[i][0], da[i], b0);
                fma2(acc[i][1], da[i], b1);
                fma2(acc[i][2], da[i], b2);
                fma2(acc[i][3], da[i], b3);
            }
        }
        if (t + 1 < nt) {
            const int nxt = cur ^ 1;
            As[nxt][a_col + 0][a_row] = na.x; As[nxt][a_col + 1][a_row] = na.y;
            As[nxt][a_col + 2][a_row] = na.z; As[nxt][a_col + 3][a_row] = na.w;
            *(float4*)&Bs[nxt][b_row][b_col] = nb;
            __syncthreads();
        }
    }

    float alpha = 1.0f;
    if (AMODE) {
        float w0 = attn[0], w1 = attn[1];
        float mx = fmaxf(w0, w1);
        float e0 = expf(w0 - mx), e1 = expf(w1 - mx);
        alpha = ((AMODE == 1) ? e0 : e1) / (e0 + e1);
    }

#pragma unroll
    for (int i = 0; i < 8; ++i) {
        const int r = m0 + ((i < 4) ? (ry * 4 + i) : (64 + ry * 4 + i - 4));
#pragma unroll
        for (int p = 0; p < 4; ++p) {
            const int c = n0 + ((p < 2) ? (cx * 4 + 2 * p)
                                        : (64 + cx * 4 + 2 * (p - 2)));
            U2 u; u.u = acc[i][p];
            float o0 = alpha * (u.f.x + bias[c]);
            float o1 = alpha * (u.f.y + bias[c + 1]);
            if (RELU) { o0 = fmaxf(o0, 0.0f); o1 = fmaxf(o1, 0.0f); }
            float* Cp = C + (size_t)r * N + c;
            if (ACCUM) { o0 += Cp[0]; o1 += Cp[1]; }
            Cp[0] = o0; Cp[1] = o1;
        }
    }
}

// =================================================================================
// Similarity GEMM via HMMA (fp16x3 split). This round: hi*hi in fp32-acc HMMA;
// the hi*lo + lo*hi corrections share ONE fp16-accumulator (2x rate if the HW
// supports it), converted and added in the epilogue. Triangular grid.
// =================================================================================
#define SIM_TILE   128
#define SIM_KC     32
#define SIM_NCH    (HIDDIM / SIM_KC)      // 16
#define SIM_TSZ    (128 * 40 * 2)         // 10240 bytes per tile (stride 80B)
#define SIM_BUFSZ  (4 * SIM_TSZ)          // Ahi,Alo,Bhi,Blo = 40960
#define SIM_SMEM   (2 * SIM_BUFSZ)        // 81920
#define SIM_NB     (NNODES / SIM_TILE)    // 64
#define SIM_GRID   (SIM_NB * (SIM_NB + 1) / 2)   // 2080

__device__ __forceinline__ void sim_stage(
    uint32_t sb, int buf, const __half* __restrict__ nh,
    const __half* __restrict__ nl, int m0, int n0, int kc0, int tid)
{
    const uint32_t bo = sb + buf * SIM_BUFSZ;
    for (int task = tid; task < 512; task += 256) {
        const int r = task >> 2, v = task & 3;
        const uint32_t d = bo + (uint32_t)(r * 80 + v * 16);
        const size_t ma = (size_t)(m0 + r) * HIDDIM + kc0 + v * 8;
        const size_t na = (size_t)(n0 + r) * HIDDIM + kc0 + v * 8;
        cpasync16(d,                nh + ma);
        cpasync16(d + SIM_TSZ,      nl + ma);
        cpasync16(d + 2 * SIM_TSZ,  nh + na);
        cpasync16(d + 3 * SIM_TSZ,  nl + na);
    }
}

__global__ void __launch_bounds__(256, 1) sim_hmma_kernel(
    const __half* __restrict__ nh, const __half* __restrict__ nl,
    float* __restrict__ sim)
{
    // triangular decode: linear block -> (by, bx) with by <= bx
    int L = blockIdx.x;
    int by = 0;
    while (L >= SIM_NB - by) { L -= SIM_NB - by; ++by; }
    const int bx = by + L;

    extern __shared__ __align__(16) char smem[];
    const uint32_t sb = smem_u32(smem);

    const int tid = threadIdx.x;
    const int wid = tid >> 5, lane = tid & 31;
    const int wr = wid >> 1, wc = wid & 1;       // 4 x 2 warps
    const int g = lane >> 2, t = lane & 3;
    const int m0 = by * SIM_TILE;
    const int n0 = bx * SIM_TILE;

    const int sub = lane >> 3, lr = lane & 7;
    const uint32_t aoff0 =
        (uint32_t)((wr * 32 + (sub & 1) * 8 + lr) * 80 + (sub >> 1) * 16);
    const uint32_t boff0 =
        (uint32_t)((wc * 64 + (sub >> 1) * 8 + lr) * 80 + (sub & 1) * 16);

    float acc[2][8][4];          // hi*hi, fp32 accumulate
    uint32_t accc[2][8][2];      // hi*lo + lo*hi, shared fp16 accumulate
#pragma unroll
    for (int i = 0; i < 2; ++i)
#pragma unroll
        for (int j = 0; j < 8; ++j) {
#pragma unroll
            for (int p = 0; p < 4; ++p) acc[i][j][p] = 0.0f;
            accc[i][j][0] = 0u; accc[i][j][1] = 0u;
        }

    sim_stage(sb, 0, nh, nl, m0, n0, 0, tid);
    CP_COMMIT();
    CP_WAIT0();
    __syncthreads();

    for (int ch = 0; ch < SIM_NCH; ++ch) {
        const int cur = ch & 1;
        if (ch + 1 < SIM_NCH) {
            sim_stage(sb, cur ^ 1, nh, nl, m0, n0, (ch + 1) * SIM_KC, tid);
            CP_COMMIT();
        }

        const uint32_t tb = sb + cur * SIM_BUFSZ;

#pragma unroll
        for (int ks = 0; ks < 2; ++ks) {
            const uint32_t ko = (uint32_t)(ks * 32);
            uint32_t ah[2][4], al[2][4];
            ldmx4(ah[0], tb + aoff0 + ko);
            ldmx4(ah[1], tb + aoff0 + 1280 + ko);
            ldmx4(al[0], tb + SIM_TSZ + aoff0 + ko);
            ldmx4(al[1], tb + SIM_TSZ + aoff0 + 1280 + ko);
#pragma unroll
            for (int jp = 0; jp < 4; ++jp) {
                uint32_t bh[4], bl[4];
                ldmx4(bh, tb + 2 * SIM_TSZ + boff0 + (uint32_t)(jp * 1280) + ko);
                ldmx4(bl, tb + 3 * SIM_TSZ + boff0 + (uint32_t)(jp * 1280) + ko);
                const int j0 = jp * 2, j1 = jp * 2 + 1;
                // main term: fp32 accumulate
                hmma(acc[0][j0], ah[0], bh[0], bh[1]);
                hmma(acc[1][j0], ah[1], bh[0], bh[1]);
                hmma(acc[0][j1], ah[0], bh[2], bh[3]);
                hmma(acc[1][j1], ah[1], bh[2], bh[3]);
                // corrections: shared fp16 accumulator (hi*lo then lo*hi)
                hmma16(accc[0][j0], ah[0], bl[0], bl[1]);
                hmma16(accc[1][j0], ah[1], bl[0], bl[1]);
                hmma16(accc[0][j1], ah[0], bl[2], bl[3]);
                hmma16(accc[1][j1], ah[1], bl[2], bl[3]);
                hmma16(accc[0][j0], al[0], bh[0], bh[1]);
                hmma16(accc[1][j0], al[1], bh[0], bh[1]);
                hmma16(accc[0][j1], al[0], bh[2], bh[3]);
                hmma16(accc[1][j1], al[1], bh[2], bh[3]);
            }
        }

        if (ch + 1 < SIM_NCH) {
            CP_WAIT0();
            __syncthreads();
        }
    }

    // ---- epilogue: add fp16 corrections, stage C tile in SMEM (stride 129),
    //      write both orientations
    __syncthreads();
    float* Cs = (float*)smem;
#pragma unroll
    for (int i = 0; i < 2; ++i) {
        const int row = wr * 32 + i * 16 + g;
#pragma unroll
        for (int j = 0; j < 8; ++j) {
            const int col = wc * 64 + j * 8 + 2 * t;
            float2 c01 = __half22float2(*(__half2*)&accc[i][j][0]);
            float2 c23 = __half22float2(*(__half2*)&accc[i][j][1]);
            Cs[row * 129 + col]           = acc[i][j][0] + c01.x;
            Cs[row * 129 + col + 1]       = acc[i][j][1] + c01.y;
            Cs[(row + 8) * 129 + col]     = acc[i][j][2] + c23.x;
            Cs[(row + 8) * 129 + col + 1] = acc[i][j][3] + c23.y;
        }
    }
    __syncthreads();

    for (int idx = tid; idx < 128 * 32; idx += 256) {
        const int r = idx >> 5, q = (idx & 31) * 4;
        float4 v;
        v.x = Cs[r * 129 + q];     v.y = Cs[r * 129 + q + 1];
        v.z = Cs[r * 129 + q + 2]; v.w = Cs[r * 129 + q + 3];
        *(float4*)&sim[(size_t)(m0 + r) * NNODES + n0 + q] = v;
    }
    if (bx != by) {
        for (int idx = tid; idx < 128 * 32; idx += 256) {
            const int c = idx >> 5, q = (idx & 31) * 4;
            float4 v;
            v.x = Cs[(q)     * 129 + c]; v.y = Cs[(q + 1) * 129 + c];
            v.z = Cs[(q + 2) * 129 + c]; v.w = Cs[(q + 3) * 129 + c];
            *(float4*)&sim[(size_t)(n0 + c) * NNODES + m0 + q] = v;
        }
    }
}

// =================================================================================
// Row stats: rowmean = mean(fused); normed emitted as hi/lo fp16 split.
// =================================================================================
__global__ void rowstats_kernel(const float* __restrict__ fused,
                                __half* __restrict__ nh,
                                __half* __restrict__ nl,
                                float* __restrict__ rowmean)
{
    const int row = blockIdx.x;
    const int tid = threadIdx.x;
    const float* fp = fused + (size_t)row * HIDDIM;
    float x0 = fp[tid], x1 = fp[tid + 256];
    float s = x0 + x1;
    float q = x0 * x0 + x1 * x1;
#pragma unroll
    for (int o = 16; o; o >>= 1) {
        s += __shfl_xor_sync(0xffffffffu, s, o);
        q += __shfl_xor_sync(0xffffffffu, q, o);
    }
    __shared__ float ss[8], qq[8];
    __shared__ float s_den;
    if ((tid & 31) == 0) { ss[tid >> 5] = s; qq[tid >> 5] = q; }
    __syncthreads();
    if (tid == 0) {
        float S = 0.0f, Q = 0.0f;
#pragma unroll
        for (int i = 0; i < 8; ++i) { S += ss[i]; Q += qq[i]; }
        s_den = fmaxf(sqrtf(Q), 1e-12f);
        rowmean[row] = S * (1.0f / HIDDIM);
    }
    __syncthreads();
    const float den = s_den;
    const size_t base = (size_t)row * HIDDIM;
    float v0 = x0 / den, v1 = x1 / den;
    __half h0v = __float2half_rn(v0);
    __half h1v = __float2half_rn(v1);
    nh[base + tid]       = h0v;
    nh[base + tid + 256] = h1v;
    nl[base + tid]       = __float2half_rn(v0 - __half2float(h0v));
    nl[base + tid + 256] = __float2half_rn(v1 - __half2float(h1v));
}

// =================================================================================
// Per-row top-17 — R9-passing version (verbatim R5 insert + merge, float4 scan).
// =================================================================================
__device__ __forceinline__ void topk_insert_r5(float v, int j, float* lv, int* li)
{
    if (v > lv[TKK - 1]) {
        int t = TKK - 1;
        while (t > 0 && lv[t - 1] < v) {
            lv[t] = lv[t - 1]; li[t] = li[t - 1]; --t;
        }
        lv[t] = v; li[t] = j;
    }
}

__global__ void topk_kernel(const float* __restrict__ sim,
                            const float* __restrict__ rowmean,
                            int* __restrict__ nbrs,
                            float* __restrict__ wout,
                            int* __restrict__ keep)
{
    const int row = blockIdx.x;
    const int tid = threadIdx.x;
    const float4* sp4 = (const float4*)(sim + (size_t)row * NNODES);

    float lv[TKK]; int li[TKK];
#pragma unroll
    for (int t = 0; t < TKK; ++t) { lv[t] = -3.4e38f; li[t] = 0x7fffffff; }

#pragma unroll 1
    for (int it = 0; it < 8; ++it) {
        const int vidx = tid + it * 256;
        float4 v4 = sp4[vidx];
        const int jb = vidx * 4;
        topk_insert_r5(v4.x, jb,     lv, li);
        topk_insert_r5(v4.y, jb + 1, lv, li);
        topk_insert_r5(v4.z, jb + 2, lv, li);
        topk_insert_r5(v4.w, jb + 3, lv, li);
    }

    __shared__ float rv[256];
    __shared__ int   ri[256];
    __shared__ int   ro[256];
    __shared__ int   sel[TKK];
    __shared__ int   s_owner;

    int head = 0;
    for (int round = 0; round < TKK; ++round) {
        rv[tid] = (head < TKK) ? lv[head] : -3.4e38f;
        ri[tid] = (head < TKK) ? li[head] : 0x7fffffff;
        ro[tid] = tid;
        __syncthreads();
        for (int s = 128; s; s >>= 1) {
            if (tid < s) {
                float v2 = rv[tid + s]; int i2 = ri[tid + s];
                if (v2 > rv[tid] || (v2 == rv[tid] && i2 < ri[tid])) {
                    rv[tid] = v2; ri[tid] = i2; ro[tid] = ro[tid + s];
                }
            }
            __syncthreads();
        }
        if (tid == 0) { sel[round] = ri[0]; s_owner = ro[0]; }
        __syncthreads();
        if (tid == s_owner) ++head;
        __syncthreads();
    }

    if (tid == 0) {
        int nb[KTOP]; int c = 0;
        for (int t = 0; t < TKK; ++t)
            if (sel[t] != row && c < KTOP) nb[c++] = sel[t];
        float s = rowmean[row];
#pragma unroll
        for (int t = 0; t < KTOP; ++t) {
            s += rowmean[nb[t]];
            nbrs[row * KTOP + t] = nb[t];
        }
        float mean = s * (1.0f / (float)TKK);
        wout[row] = 1.0f / (1.0f + expf(-mean));
        keep[row] = (mean > 0.0f) ? 1 : 0;
    }
}

// ---------------- output zero + scatter ----------------
__global__ void zero_kernel(float* __restrict__ p, long long n)
{
    long long n4 = n >> 2;
    float4* p4 = (float4*)p;
    long long i = (long long)blockIdx.x * blockDim.x + threadIdx.x;
    long long stride = (long long)gridDim.x * blockDim.x;
    float4 z = make_float4(0.f, 0.f, 0.f, 0.f);
    for (; i < n4; i += stride) p4[i] = z;
    if (blockIdx.x == 0 && threadIdx.x == 0)
        for (long long t = n4 << 2; t < n; ++t) p[t] = 0.f;
}

__global__ void scatter_kernel(const int* __restrict__ nbrs,
                               const float* __restrict__ w,
                               const int* __restrict__ keep,
                               float* __restrict__ out)
{
    const int i = blockIdx.x * blockDim.x + threadIdx.x;
    if (i >= NNODES) return;
    const int kp = keep[i];
    out[(size_t)NNODES * NNODES + i] = kp ? w[i] : 0.0f;
    if (kp) {
        out[(size_t)i * NNODES + i] = 1.0f;
#pragma unroll
        for (int t = 0; t < KTOP; ++t) {
            int n = nbrs[i * KTOP + t];
            out[(size_t)n * NNODES + i] = 1.0f;
        }
    }
}

// =================================================================================
extern "C" void kernel_launch(void* const* d_in, const int* in_sizes, int n_in,
                              void* d_out, int out_size)
{
    const float* x0   = (const float*)d_in[0];
    const float* x1   = (const float*)d_in[1];
    const float* w1_0 = (const float*)d_in[2];
    const float* b1_0 = (const float*)d_in[3];
    const float* w2_0 = (const float*)d_in[4];
    const float* b2_0 = (const float*)d_in[5];
    const float* w1_1 = (const float*)d_in[6];
    const float* b1_1 = (const float*)d_in[7];
    const float* w2_1 = (const float*)d_in[8];
    const float* b2_1 = (const float*)d_in[9];
    const float* attn = (const float*)d_in[10];
    const float* fw   = (const float*)d_in[11];
    const float* fb   = (const float*)d_in[12];
    float* out = (float*)d_out;

    float *h0, *h1, *f, *fused, *rowmean, *sim, *wv;
    __half *nh, *nl;
    int *nbrs, *keep;
    cudaGetSymbolAddress((void**)&h0, g_h0);
    cudaGetSymbolAddress((void**)&h1, g_h1);
    cudaGetSymbolAddress((void**)&f, g_f);
    cudaGetSymbolAddress((void**)&fused, g_fused);
    cudaGetSymbolAddress((void**)&nh, g_nh);
    cudaGetSymbolAddress((void**)&nl, g_nl);
    cudaGetSymbolAddress((void**)&rowmean, g_rowmean);
    cudaGetSymbolAddress((void**)&sim, g_sim);
    cudaGetSymbolAddress((void**)&nbrs, g_nbrs);
    cudaGetSymbolAddress((void**)&wv, g_w);
    cudaGetSymbolAddress((void**)&keep, g_keep);

    cudaFuncSetAttribute(sim_hmma_kernel,
                         cudaFuncAttributeMaxDynamicSharedMemorySize, SIM_SMEM);

    const long long total_out = (long long)NNODES * NNODES + NNODES;
    zero_kernel<<<4096, 256>>>(out, total_out);

    dim3 blk(256);
    // layer 1 (ReLU)
    gemm_nn<1, 0, 0><<<dim3(HIDDIM / 128, NNODES / 128), blk>>>(
        x0, w1_0, b1_0, nullptr, h0, NNODES, HIDDIM, 512);
    gemm_nn<1, 0, 0><<<dim3(HIDDIM / 128, NNODES / 128), blk>>>(
        x1, w1_1, b1_1, nullptr, h1, NNODES, HIDDIM, 768);
    // layer 2 scaled by softmax(attn): f = a0*(h0@w2_0+b2_0) + a1*(h1@w2_1+b2_1)
    gemm_nn<0, 1, 0><<<dim3(HIDDIM / 128, NNODES / 128), blk>>>(
        h0, w2_0, b2_0, attn, f, NNODES, HIDDIM, HIDDIM);
    gemm_nn<0, 2, 1><<<dim3(HIDDIM / 128, NNODES / 128), blk>>>(
        h1, w2_1, b2_1, attn, f, NNODES, HIDDIM, HIDDIM);
    // fusion
    gemm_nn<0, 0, 0><<<dim3(HIDDIM / 128, NNODES / 128), blk>>>(
        f, fw, fb, nullptr, fused, NNODES, HIDDIM, HIDDIM);

    rowstats_kernel<<<NNODES, 256>>>(fused, nh, nl, rowmean);

    sim_hmma_kernel<<<SIM_GRID, blk, SIM_SMEM>>>(nh, nl, sim);

    topk_kernel<<<NNODES, 256>>>(sim, rowmean, nbrs, wv, keep);

    scatter_kernel<<<(NNODES + 255) / 256, 256>>>(nbrs, wv, keep, out);
}

// round 12
// speedup vs baseline: 1.0005x; 1.0005x over previous
#include <cuda_runtime.h>
#include <cuda_fp16.h>
#include <math.h>
#include <stdint.h>

#define NNODES 8192
#define HIDDIM 512
#define KTOP   16
#define TKK    17   // top_k + 1

// ---------------- scratch (static __device__ — no allocations allowed) ----------
__device__ float  g_h0[NNODES * HIDDIM];
__device__ float  g_h1[NNODES * HIDDIM];
__device__ float  g_f [NNODES * HIDDIM];
__device__ float  g_fused [NNODES * HIDDIM];
__device__ __half g_nh[NNODES * HIDDIM];   // hi half of normed
__device__ __half g_nl[NNODES * HIDDIM];   // lo half of normed
__device__ float  g_rowmean[NNODES];
__device__ float  g_sim[(size_t)NNODES * NNODES];
__device__ int    g_nbrs[NNODES * KTOP];
__device__ float  g_w[NNODES];
__device__ int    g_keep[NNODES];

// ---------------- packed f32x2 helpers (fp32 FMA path for MLP GEMMs) ------------
__device__ __forceinline__ unsigned long long dup2(float x) {
    unsigned long long r;
    asm("mov.b64 %0, {%1, %1};" : "=l"(r) : "f"(x));
    return r;
}
__device__ __forceinline__ void fma2(unsigned long long &c,
                                     unsigned long long a,
                                     unsigned long long b) {
    asm("fma.rn.f32x2 %0, %1, %2, %3;" : "=l"(c) : "l"(a), "l"(b), "l"(c));
}
union U2 { unsigned long long u; float2 f; };

// ---------------- HMMA + cp.async + ldmatrix helpers (sm_80+, sm_100-safe) ------
__device__ __forceinline__ void hmma(float* c,
                                     const uint32_t* a,
                                     uint32_t b0, uint32_t b1) {
    asm volatile(
        "mma.sync.aligned.m16n8k16.row.col.f32.f16.f16.f32 "
        "{%0,%1,%2,%3}, {%4,%5,%6,%7}, {%8,%9}, {%0,%1,%2,%3};"
        : "+f"(c[0]), "+f"(c[1]), "+f"(c[2]), "+f"(c[3])
        : "r"(a[0]), "r"(a[1]), "r"(a[2]), "r"(a[3]), "r"(b0), "r"(b1));
}
__device__ __forceinline__ void ldmx4(uint32_t* d, uint32_t addr) {
    asm volatile(
        "ldmatrix.sync.aligned.m8n8.x4.shared.b16 {%0,%1,%2,%3}, [%4];"
        : "=r"(d[0]), "=r"(d[1]), "=r"(d[2]), "=r"(d[3]) : "r"(addr));
}
__device__ __forceinline__ uint32_t smem_u32(const void* p) {
    uint32_t a;
    asm("{ .reg .u64 t; cvta.to.shared.u64 t, %1; cvt.u32.u64 %0, t; }"
        : "=r"(a) : "l"(p));
    return a;
}
__device__ __forceinline__ void cpasync16(uint32_t dst, const void* src) {
    asm volatile("cp.async.cg.shared.global [%0], [%1], 16;"
                 :: "r"(dst), "l"(src));
}
#define CP_COMMIT() asm volatile("cp.async.commit_group;" ::: "memory")
#define CP_WAIT0()  asm volatile("cp.async.wait_group 0;" ::: "memory")

// =================================================================================
// GEMM NN (fp32, f32x2 FMA path), BK=16: doubled prefetch window per LDG to cover
// L2 latency (fma was 61% due to exposed loads at BK=8); per-thread k-accumulation
// order is IDENTICAL to the BK=8 version -> bit-identical outputs.
// =================================================================================
template<int RELU, int AMODE, int ACCUM>
__global__ void __launch_bounds__(256, 2) gemm_nn(
    const float* __restrict__ A, const float* __restrict__ B,
    const float* __restrict__ bias, const float* __restrict__ attn,
    float* __restrict__ C, int M, int N, int K)
{
    __shared__ __align__(16) float As[2][16][128];
    __shared__ __align__(16) float Bs[2][16][128];

    const int tid = threadIdx.x;
    const int m0 = blockIdx.y * 128;
    const int n0 = blockIdx.x * 128;

    const int a_row = tid >> 1, a_col = (tid & 1) * 8;
    const int b_row = tid >> 4, b_col = (tid & 15) * 8;
    const float* Ap = A + (size_t)(m0 + a_row) * K + a_col;
    const float* Bp = B + (size_t)b_row * N + n0 + b_col;

    {
        float4 a0 = *(const float4*)Ap;
        float4 a1 = *(const float4*)(Ap + 4);
        float4 bb0 = *(const float4*)Bp;
        float4 bb1 = *(const float4*)(Bp + 4);
        As[0][a_col + 0][a_row] = a0.x; As[0][a_col + 1][a_row] = a0.y;
        As[0][a_col + 2][a_row] = a0.z; As[0][a_col + 3][a_row] = a0.w;
        As[0][a_col + 4][a_row] = a1.x; As[0][a_col + 5][a_row] = a1.y;
        As[0][a_col + 6][a_row] = a1.z; As[0][a_col + 7][a_row] = a1.w;
        *(float4*)&Bs[0][b_row][b_col]     = bb0;
        *(float4*)&Bs[0][b_row][b_col + 4] = bb1;
    }
    __syncthreads();

    const int ry = tid >> 4;
    const int cx = tid & 15;

    unsigned long long acc[8][4];
#pragma unroll
    for (int i = 0; i < 8; ++i)
#pragma unroll
        for (int p = 0; p < 4; ++p) acc[i][p] = 0ull;

    const int nt = K >> 4;
    for (int t = 0; t < nt; ++t) {
        const int cur = t & 1;
        float4 na0, na1, nb0, nb1;
        if (t + 1 < nt) {
            const float* Apn = Ap + (t + 1) * 16;
            const float* Bpn = Bp + (size_t)(t + 1) * 16 * N;
            na0 = *(const float4*)Apn;
            na1 = *(const float4*)(Apn + 4);
            nb0 = *(const float4*)Bpn;
            nb1 = *(const float4*)(Bpn + 4);
        }
#pragma unroll
        for (int k = 0; k < 16; ++k) {
            float4 aA = *(const float4*)&As[cur][k][ry * 4];
            float4 aB = *(const float4*)&As[cur][k][64 + ry * 4];
            const unsigned long long* bp0 =
                (const unsigned long long*)&Bs[cur][k][cx * 4];
            const unsigned long long* bp1 =
                (const unsigned long long*)&Bs[cur][k][64 + cx * 4];
            unsigned long long b0 = bp0[0], b1 = bp0[1];
            unsigned long long b2 = bp1[0], b3 = bp1[1];
            unsigned long long da[8] = {
                dup2(aA.x), dup2(aA.y), dup2(aA.z), dup2(aA.w),
                dup2(aB.x), dup2(aB.y), dup2(aB.z), dup2(aB.w)
            };
#pragma unroll
            for (int i = 0; i < 8; ++i) {
                fma2(acc[i][0], da[i], b0);
                fma2(acc[i][1], da[i], b1);
                fma2(acc[i][2], da[i], b2);
                fma2(acc[i][3], da[i], b3);
            }
        }
        if (t + 1 < nt) {
            const int nxt = cur ^ 1;
            As[nxt][a_col + 0][a_row] = na0.x; As[nxt][a_col + 1][a_row] = na0.y;
            As[nxt][a_col + 2][a_row] = na0.z; As[nxt][a_col + 3][a_row] = na0.w;
            As[nxt][a_col + 4][a_row] = na1.x; As[nxt][a_col + 5][a_row] = na1.y;
            As[nxt][a_col + 6][a_row] = na1.z; As[nxt][a_col + 7][a_row] = na1.w;
            *(float4*)&Bs[nxt][b_row][b_col]     = nb0;
            *(float4*)&Bs[nxt][b_row][b_col + 4] = nb1;
            __syncthreads();
        }
    }

    float alpha = 1.0f;
    if (AMODE) {
        float w0 = attn[0], w1 = attn[1];
        float mx = fmaxf(w0, w1);
        float e0 = expf(w0 - mx), e1 = expf(w1 - mx);
        alpha = ((AMODE == 1) ? e0 : e1) / (e0 + e1);
    }

#pragma unroll
    for (int i = 0; i < 8; ++i) {
        const int r = m0 + ((i < 4) ? (ry * 4 + i) : (64 + ry * 4 + i - 4));
#pragma unroll
        for (int p = 0; p < 4; ++p) {
            const int c = n0 + ((p < 2) ? (cx * 4 + 2 * p)
                                        : (64 + cx * 4 + 2 * (p - 2)));
            U2 u; u.u = acc[i][p];
            float o0 = alpha * (u.f.x + bias[c]);
            float o1 = alpha * (u.f.y + bias[c + 1]);
            if (RELU) { o0 = fmaxf(o0, 0.0f); o1 = fmaxf(o1, 0.0f); }
            float* Cp = C + (size_t)r * N + c;
            if (ACCUM) { o0 += Cp[0]; o1 += Cp[1]; }
            Cp[0] = o0; Cp[1] = o1;
        }
    }
}

// =================================================================================
// Similarity GEMM via HMMA — R9-PASSING VERSION VERBATIM (fp32-acc 3-term,
// ldmatrix.x4, triangular grid, occupancy 2). Legacy-HMMA pipe-rate bound.
// =================================================================================
#define SIM_TILE   128
#define SIM_KC     32
#define SIM_NCH    (HIDDIM / SIM_KC)      // 16
#define SIM_TSZ    (128 * 40 * 2)         // 10240 bytes per tile (stride 80B)
#define SIM_BUFSZ  (4 * SIM_TSZ)          // Ahi,Alo,Bhi,Blo = 40960
#define SIM_SMEM   (2 * SIM_BUFSZ)        // 81920
#define SIM_NB     (NNODES / SIM_TILE)    // 64
#define SIM_GRID   (SIM_NB * (SIM_NB + 1) / 2)   // 2080

__device__ __forceinline__ void sim_stage(
    uint32_t sb, int buf, const __half* __restrict__ nh,
    const __half* __restrict__ nl, int m0, int n0, int kc0, int tid)
{
    const uint32_t bo = sb + buf * SIM_BUFSZ;
    for (int task = tid; task < 512; task += 256) {
        const int r = task >> 2, v = task & 3;
        const uint32_t d = bo + (uint32_t)(r * 80 + v * 16);
        const size_t ma = (size_t)(m0 + r) * HIDDIM + kc0 + v * 8;
        const size_t na = (size_t)(n0 + r) * HIDDIM + kc0 + v * 8;
        cpasync16(d,                nh + ma);
        cpasync16(d + SIM_TSZ,      nl + ma);
        cpasync16(d + 2 * SIM_TSZ,  nh + na);
        cpasync16(d + 3 * SIM_TSZ,  nl + na);
    }
}

__global__ void __launch_bounds__(256, 2) sim_hmma_kernel(
    const __half* __restrict__ nh, const __half* __restrict__ nl,
    float* __restrict__ sim)
{
    // triangular decode: linear block -> (by, bx) with by <= bx
    int L = blockIdx.x;
    int by = 0;
    while (L >= SIM_NB - by) { L -= SIM_NB - by; ++by; }
    const int bx = by + L;

    extern __shared__ __align__(16) char smem[];
    const uint32_t sb = smem_u32(smem);

    const int tid = threadIdx.x;
    const int wid = tid >> 5, lane = tid & 31;
    const int wr = wid >> 1, wc = wid & 1;       // 4 x 2 warps
    const int g = lane >> 2, t = lane & 3;
    const int m0 = by * SIM_TILE;
    const int n0 = bx * SIM_TILE;

    const int sub = lane >> 3, lr = lane & 7;
    const uint32_t aoff0 =
        (uint32_t)((wr * 32 + (sub & 1) * 8 + lr) * 80 + (sub >> 1) * 16);
    const uint32_t boff0 =
        (uint32_t)((wc * 64 + (sub >> 1) * 8 + lr) * 80 + (sub & 1) * 16);

    float acc[2][8][4];
#pragma unroll
    for (int i = 0; i < 2; ++i)
#pragma unroll
        for (int j = 0; j < 8; ++j)
#pragma unroll
            for (int p = 0; p < 4; ++p) acc[i][j][p] = 0.0f;

    sim_stage(sb, 0, nh, nl, m0, n0, 0, tid);
    CP_COMMIT();
    CP_WAIT0();
    __syncthreads();

    for (int ch = 0; ch < SIM_NCH; ++ch) {
        const int cur = ch & 1;
        if (ch + 1 < SIM_NCH) {
            sim_stage(sb, cur ^ 1, nh, nl, m0, n0, (ch + 1) * SIM_KC, tid);
            CP_COMMIT();
        }

        const uint32_t tb = sb + cur * SIM_BUFSZ;

#pragma unroll
        for (int ks = 0; ks < 2; ++ks) {
            const uint32_t ko = (uint32_t)(ks * 32);
            uint32_t ah[2][4], al[2][4];
            ldmx4(ah[0], tb + aoff0 + ko);
            ldmx4(ah[1], tb + aoff0 + 1280 + ko);
            ldmx4(al[0], tb + SIM_TSZ + aoff0 + ko);
            ldmx4(al[1], tb + SIM_TSZ + aoff0 + 1280 + ko);
#pragma unroll
            for (int jp = 0; jp < 4; ++jp) {
                uint32_t bh[4], bl[4];
                ldmx4(bh, tb + 2 * SIM_TSZ + boff0 + (uint32_t)(jp * 1280) + ko);
                ldmx4(bl, tb + 3 * SIM_TSZ + boff0 + (uint32_t)(jp * 1280) + ko);
                const int j0 = jp * 2, j1 = jp * 2 + 1;
                hmma(acc[0][j0], ah[0], bh[0], bh[1]);
                hmma(acc[1][j0], ah[1], bh[0], bh[1]);
                hmma(acc[0][j1], ah[0], bh[2], bh[3]);
                hmma(acc[1][j1], ah[1], bh[2], bh[3]);
                hmma(acc[0][j0], ah[0], bl[0], bl[1]);
                hmma(acc[1][j0], ah[1], bl[0], bl[1]);
                hmma(acc[0][j1], ah[0], bl[2], bl[3]);
                hmma(acc[1][j1], ah[1], bl[2], bl[3]);
                hmma(acc[0][j0], al[0], bh[0], bh[1]);
                hmma(acc[1][j0], al[1], bh[0], bh[1]);
                hmma(acc[0][j1], al[0], bh[2], bh[3]);
                hmma(acc[1][j1], al[1], bh[2], bh[3]);
            }
        }

        if (ch + 1 < SIM_NCH) {
            CP_WAIT0();
            __syncthreads();
        }
    }

    // ---- epilogue: stage C tile in SMEM (stride 129), write both orientations
    __syncthreads();
    float* Cs = (float*)smem;
#pragma unroll
    for (int i = 0; i < 2; ++i) {
        const int row = wr * 32 + i * 16 + g;
#pragma unroll
        for (int j = 0; j < 8; ++j) {
            const int col = wc * 64 + j * 8 + 2 * t;
            Cs[row * 129 + col]           = acc[i][j][0];
            Cs[row * 129 + col + 1]       = acc[i][j][1];
            Cs[(row + 8) * 129 + col]     = acc[i][j][2];
            Cs[(row + 8) * 129 + col + 1] = acc[i][j][3];
        }
    }
    __syncthreads();

    for (int idx = tid; idx < 128 * 32; idx += 256) {
        const int r = idx >> 5, q = (idx & 31) * 4;
        float4 v;
        v.x = Cs[r * 129 + q];     v.y = Cs[r * 129 + q + 1];
        v.z = Cs[r * 129 + q + 2]; v.w = Cs[r * 129 + q + 3];
        *(float4*)&sim[(size_t)(m0 + r) * NNODES + n0 + q] = v;
    }
    if (bx != by) {
        for (int idx = tid; idx < 128 * 32; idx += 256) {
            const int c = idx >> 5, q = (idx & 31) * 4;
            float4 v;
            v.x = Cs[(q)     * 129 + c]; v.y = Cs[(q + 1) * 129 + c];
            v.z = Cs[(q + 2) * 129 + c]; v.w = Cs[(q + 3) * 129 + c];
            *(float4*)&sim[(size_t)(n0 + c) * NNODES + m0 + q] = v;
        }
    }
}

// =================================================================================
// Row stats: rowmean = mean(fused); normed emitted as hi/lo fp16 split.
// =================================================================================
__global__ void rowstats_kernel(const float* __restrict__ fused,
                                __half* __restrict__ nh,
                                __half* __restrict__ nl,
                                float* __restrict__ rowmean)
{
    const int row = blockIdx.x;
    const int tid = threadIdx.x;
    const float* fp = fused + (size_t)row * HIDDIM;
    float x0 = fp[tid], x1 = fp[tid + 256];
    float s = x0 + x1;
    float q = x0 * x0 + x1 * x1;
#pragma unroll
    for (int o = 16; o; o >>= 1) {
        s += __shfl_xor_sync(0xffffffffu, s, o);
        q += __shfl_xor_sync(0xffffffffu, q, o);
    }
    __shared__ float ss[8], qq[8];
    __shared__ float s_den;
    if ((tid & 31) == 0) { ss[tid >> 5] = s; qq[tid >> 5] = q; }
    __syncthreads();
    if (tid == 0) {
        float S = 0.0f, Q = 0.0f;
#pragma unroll
        for (int i = 0; i < 8; ++i) { S += ss[i]; Q += qq[i]; }
        s_den = fmaxf(sqrtf(Q), 1e-12f);
        rowmean[row] = S * (1.0f / HIDDIM);
    }
    __syncthreads();
    const float den = s_den;
    const size_t base = (size_t)row * HIDDIM;
    float v0 = x0 / den, v1 = x1 / den;
    __half h0v = __float2half_rn(v0);
    __half h1v = __float2half_rn(v1);
    nh[base + tid]       = h0v;
    nh[base + tid + 256] = h1v;
    nl[base + tid]       = __float2half_rn(v0 - __half2float(h0v));
    nl[base + tid + 256] = __float2half_rn(v1 - __half2float(h1v));
}

// =================================================================================
// Per-row top-17 — R9-passing version (verbatim R5 insert + merge, float4 scan).
// =================================================================================
__device__ __forceinline__ void topk_insert_r5(float v, int j, float* lv, int* li)
{
    if (v > lv[TKK - 1]) {
        int t = TKK - 1;
        while (t > 0 && lv[t - 1] < v) {
            lv[t] = lv[t - 1]; li[t] = li[t - 1]; --t;
        }
        lv[t] = v; li[t] = j;
    }
}

__global__ void topk_kernel(const float* __restrict__ sim,
                            const float* __restrict__ rowmean,
                            int* __restrict__ nbrs,
                            float* __restrict__ wout,
                            int* __restrict__ keep)
{
    const int row = blockIdx.x;
    const int tid = threadIdx.x;
    const float4* sp4 = (const float4*)(sim + (size_t)row * NNODES);

    float lv[TKK]; int li[TKK];
#pragma unroll
    for (int t = 0; t < TKK; ++t) { lv[t] = -3.4e38f; li[t] = 0x7fffffff; }

#pragma unroll 1
    for (int it = 0; it < 8; ++it) {
        const int vidx = tid + it * 256;
        float4 v4 = sp4[vidx];
        const int jb = vidx * 4;
        topk_insert_r5(v4.x, jb,     lv, li);
        topk_insert_r5(v4.y, jb + 1, lv, li);
        topk_insert_r5(v4.z, jb + 2, lv, li);
        topk_insert_r5(v4.w, jb + 3, lv, li);
    }

    __shared__ float rv[256];
    __shared__ int   ri[256];
    __shared__ int   ro[256];
    __shared__ int   sel[TKK];
    __shared__ int   s_owner;

    int head = 0;
    for (int round = 0; round < TKK; ++round) {
        rv[tid] = (head < TKK) ? lv[head] : -3.4e38f;
        ri[tid] = (head < TKK) ? li[head] : 0x7fffffff;
        ro[tid] = tid;
        __syncthreads();
        for (int s = 128; s; s >>= 1) {
            if (tid < s) {
                float v2 = rv[tid + s]; int i2 = ri[tid + s];
                if (v2 > rv[tid] || (v2 == rv[tid] && i2 < ri[tid])) {
                    rv[tid] = v2; ri[tid] = i2; ro[tid] = ro[tid + s];
                }
            }
            __syncthreads();
        }
        if (tid == 0) { sel[round] = ri[0]; s_owner = ro[0]; }
        __syncthreads();
        if (tid == s_owner) ++head;
        __syncthreads();
    }

    if (tid == 0) {
        int nb[KTOP]; int c = 0;
        for (int t = 0; t < TKK; ++t)
            if (sel[t] != row && c < KTOP) nb[c++] = sel[t];
        float s = rowmean[row];
#pragma unroll
        for (int t = 0; t < KTOP; ++t) {
            s += rowmean[nb[t]];
            nbrs[row * KTOP + t] = nb[t];
        }
        float mean = s * (1.0f / (float)TKK);
        wout[row] = 1.0f / (1.0f + expf(-mean));
        keep[row] = (mean > 0.0f) ? 1 : 0;
    }
}

// ---------------- output zero + scatter ----------------
__global__ void zero_kernel(float* __restrict__ p, long long n)
{
    long long n4 = n >> 2;
    float4* p4 = (float4*)p;
    long long i = (long long)blockIdx.x * blockDim.x + threadIdx.x;
    long long stride = (long long)gridDim.x * blockDim.x;
    float4 z = make_float4(0.f, 0.f, 0.f, 0.f);
    for (; i < n4; i += stride) p4[i] = z;
    if (blockIdx.x == 0 && threadIdx.x == 0)
        for (long long t = n4 << 2; t < n; ++t) p[t] = 0.f;
}

__global__ void scatter_kernel(const int* __restrict__ nbrs,
                               const float* __restrict__ w,
                               const int* __restrict__ keep,
                               float* __restrict__ out)
{
    const int i = blockIdx.x * blockDim.x + threadIdx.x;
    if (i >= NNODES) return;
    const int kp = keep[i];
    out[(size_t)NNODES * NNODES + i] = kp ? w[i] : 0.0f;
    if (kp) {
        out[(size_t)i * NNODES + i] = 1.0f;
#pragma unroll
        for (int t = 0; t < KTOP; ++t) {
            int n = nbrs[i * KTOP + t];
            out[(size_t)n * NNODES + i] = 1.0f;
        }
    }
}

// =================================================================================
extern "C" void kernel_launch(void* const* d_in, const int* in_sizes, int n_in,
                              void* d_out, int out_size)
{
    const float* x0   = (const float*)d_in[0];
    const float* x1   = (const float*)d_in[1];
    const float* w1_0 = (const float*)d_in[2];
    const float* b1_0 = (const float*)d_in[3];
    const float* w2_0 = (const float*)d_in[4];
    const float* b2_0 = (const float*)d_in[5];
    const float* w1_1 = (const float*)d_in[6];
    const float* b1_1 = (const float*)d_in[7];
    const float* w2_1 = (const float*)d_in[8];
    const float* b2_1 = (const float*)d_in[9];
    const float* attn = (const float*)d_in[10];
    const float* fw   = (const float*)d_in[11];
    const float* fb   = (const float*)d_in[12];
    float* out = (float*)d_out;

    float *h0, *h1, *f, *fused, *rowmean, *sim, *wv;
    __half *nh, *nl;
    int *nbrs, *keep;
    cudaGetSymbolAddress((void**)&h0, g_h0);
    cudaGetSymbolAddress((void**)&h1, g_h1);
    cudaGetSymbolAddress((void**)&f, g_f);
    cudaGetSymbolAddress((void**)&fused, g_fused);
    cudaGetSymbolAddress((void**)&nh, g_nh);
    cudaGetSymbolAddress((void**)&nl, g_nl);
    cudaGetSymbolAddress((void**)&rowmean, g_rowmean);
    cudaGetSymbolAddress((void**)&sim, g_sim);
    cudaGetSymbolAddress((void**)&nbrs, g_nbrs);
    cudaGetSymbolAddress((void**)&wv, g_w);
    cudaGetSymbolAddress((void**)&keep, g_keep);

    cudaFuncSetAttribute(sim_hmma_kernel,
                         cudaFuncAttributeMaxDynamicSharedMemorySize, SIM_SMEM);

    const long long total_out = (long long)NNODES * NNODES + NNODES;
    zero_kernel<<<4096, 256>>>(out, total_out);

    dim3 blk(256);
    // layer 1 (ReLU)
    gemm_nn<1, 0, 0><<<dim3(HIDDIM / 128, NNODES / 128), blk>>>(
        x0, w1_0, b1_0, nullptr, h0, NNODES, HIDDIM, 512);
    gemm_nn<1, 0, 0><<<dim3(HIDDIM / 128, NNODES / 128), blk>>>(
        x1, w1_1, b1_1, nullptr, h1, NNODES, HIDDIM, 768);
    // layer 2 scaled by softmax(attn): f = a0*(h0@w2_0+b2_0) + a1*(h1@w2_1+b2_1)
    gemm_nn<0, 1, 0><<<dim3(HIDDIM / 128, NNODES / 128), blk>>>(
        h0, w2_0, b2_0, attn, f, NNODES, HIDDIM, HIDDIM);
    gemm_nn<0, 2, 1><<<dim3(HIDDIM / 128, NNODES / 128), blk>>>(
        h1, w2_1, b2_1, attn, f, NNODES, HIDDIM, HIDDIM);
    // fusion
    gemm_nn<0, 0, 0><<<dim3(HIDDIM / 128, NNODES / 128), blk>>>(
        f, fw, fb, nullptr, fused, NNODES, HIDDIM, HIDDIM);

    rowstats_kernel<<<NNODES, 256>>>(fused, nh, nl, rowmean);

    sim_hmma_kernel<<<SIM_GRID, blk, SIM_SMEM>>>(nh, nl, sim);

    topk_kernel<<<NNODES, 256>>>(sim, rowmean, nbrs, wv, keep);

    scatter_kernel<<<(NNODES + 255) / 256, 256>>>(nbrs, wv, keep, out);
}

// round 13
// speedup vs baseline: 1.0793x; 1.0788x over previous
#include <cuda_runtime.h>
#include <cuda_fp16.h>
#include <math.h>
#include <stdint.h>

#define NNODES 8192
#define HIDDIM 512
#define KTOP   16
#define TKK    17   // top_k + 1

// ---------------- scratch (static __device__ — no allocations allowed) ----------
__device__ float  g_h0[NNODES * HIDDIM];
__device__ float  g_h1[NNODES * HIDDIM];
__device__ float  g_f [NNODES * HIDDIM];
__device__ float  g_fused [NNODES * HIDDIM];
__device__ __half g_nh[NNODES * HIDDIM];   // hi half of normed
__device__ __half g_nl[NNODES * HIDDIM];   // lo half of normed
__device__ float  g_rowmean[NNODES];
__device__ float  g_sim[(size_t)NNODES * NNODES];
__device__ int    g_nbrs[NNODES * KTOP];
__device__ float  g_w[NNODES];
__device__ int    g_keep[NNODES];

// ---------------- packed f32x2 helpers (fp32 FMA path for MLP GEMMs) ------------
__device__ __forceinline__ unsigned long long dup2(float x) {
    unsigned long long r;
    asm("mov.b64 %0, {%1, %1};" : "=l"(r) : "f"(x));
    return r;
}
__device__ __forceinline__ void fma2(unsigned long long &c,
                                     unsigned long long a,
                                     unsigned long long b) {
    asm("fma.rn.f32x2 %0, %1, %2, %3;" : "=l"(c) : "l"(a), "l"(b), "l"(c));
}
union U2 { unsigned long long u; float2 f; };

// ---------------- HMMA + cp.async + ldmatrix helpers (sm_80+, sm_100-safe) ------
__device__ __forceinline__ void hmma(float* c,
                                     const uint32_t* a,
                                     uint32_t b0, uint32_t b1) {
    asm volatile(
        "mma.sync.aligned.m16n8k16.row.col.f32.f16.f16.f32 "
        "{%0,%1,%2,%3}, {%4,%5,%6,%7}, {%8,%9}, {%0,%1,%2,%3};"
        : "+f"(c[0]), "+f"(c[1]), "+f"(c[2]), "+f"(c[3])
        : "r"(a[0]), "r"(a[1]), "r"(a[2]), "r"(a[3]), "r"(b0), "r"(b1));
}
__device__ __forceinline__ void ldmx4(uint32_t* d, uint32_t addr) {
    asm volatile(
        "ldmatrix.sync.aligned.m8n8.x4.shared.b16 {%0,%1,%2,%3}, [%4];"
        : "=r"(d[0]), "=r"(d[1]), "=r"(d[2]), "=r"(d[3]) : "r"(addr));
}
__device__ __forceinline__ uint32_t smem_u32(const void* p) {
    uint32_t a;
    asm("{ .reg .u64 t; cvta.to.shared.u64 t, %1; cvt.u32.u64 %0, t; }"
        : "=r"(a) : "l"(p));
    return a;
}
__device__ __forceinline__ void cpasync16(uint32_t dst, const void* src) {
    asm volatile("cp.async.cg.shared.global [%0], [%1], 16;"
                 :: "r"(dst), "l"(src));
}
#define CP_COMMIT() asm volatile("cp.async.commit_group;" ::: "memory")
#define CP_WAIT0()  asm volatile("cp.async.wait_group 0;" ::: "memory")

// =================================================================================
// GEMM NN (fp32, f32x2 FMA path) — R9-passing BK=8 version VERBATIM (BK=16 was a
// regression; the kernel is shared-path bound, not prefetch-window bound).
// =================================================================================
template<int RELU, int AMODE, int ACCUM>
__global__ void __launch_bounds__(256, 2) gemm_nn(
    const float* __restrict__ A, const float* __restrict__ B,
    const float* __restrict__ bias, const float* __restrict__ attn,
    float* __restrict__ C, int M, int N, int K)
{
    __shared__ __align__(16) float As[2][8][128];
    __shared__ __align__(16) float Bs[2][8][128];

    const int tid = threadIdx.x;
    const int m0 = blockIdx.y * 128;
    const int n0 = blockIdx.x * 128;

    const int a_row = tid >> 1, a_col = (tid & 1) * 4;
    const int b_row = tid >> 5, b_col = (tid & 31) * 4;
    const float* Ap = A + (size_t)(m0 + a_row) * K + a_col;
    const float* Bp = B + (size_t)b_row * N + n0 + b_col;

    {
        float4 a4 = *(const float4*)Ap;
        float4 b4 = *(const float4*)Bp;
        As[0][a_col + 0][a_row] = a4.x; As[0][a_col + 1][a_row] = a4.y;
        As[0][a_col + 2][a_row] = a4.z; As[0][a_col + 3][a_row] = a4.w;
        *(float4*)&Bs[0][b_row][b_col] = b4;
    }
    __syncthreads();

    const int ry = tid >> 4;
    const int cx = tid & 15;

    unsigned long long acc[8][4];
#pragma unroll
    for (int i = 0; i < 8; ++i)
#pragma unroll
        for (int p = 0; p < 4; ++p) acc[i][p] = 0ull;

    const int nt = K >> 3;
    for (int t = 0; t < nt; ++t) {
        const int cur = t & 1;
        float4 na, nb;
        if (t + 1 < nt) {
            na = *(const float4*)(Ap + (t + 1) * 8);
            nb = *(const float4*)(Bp + (size_t)(t + 1) * 8 * N);
        }
#pragma unroll
        for (int k = 0; k < 8; ++k) {
            float4 aA = *(const float4*)&As[cur][k][ry * 4];
            float4 aB = *(const float4*)&As[cur][k][64 + ry * 4];
            const unsigned long long* bp0 =
                (const unsigned long long*)&Bs[cur][k][cx * 4];
            const unsigned long long* bp1 =
                (const unsigned long long*)&Bs[cur][k][64 + cx * 4];
            unsigned long long b0 = bp0[0], b1 = bp0[1];
            unsigned long long b2 = bp1[0], b3 = bp1[1];
            unsigned long long da[8] = {
                dup2(aA.x), dup2(aA.y), dup2(aA.z), dup2(aA.w),
                dup2(aB.x), dup2(aB.y), dup2(aB.z), dup2(aB.w)
            };
#pragma unroll
            for (int i = 0; i < 8; ++i) {
                fma2(acc[i][0], da[i], b0);
                fma2(acc[i][1], da[i], b1);
                fma2(acc[i][2], da[i], b2);
                fma2(acc[i][3], da[i], b3);
            }
        }
        if (t + 1 < nt) {
            const int nxt = cur ^ 1;
            As[nxt][a_col + 0][a_row] = na.x; As[nxt][a_col + 1][a_row] = na.y;
            As[nxt][a_col + 2][a_row] = na.z; As[nxt][a_col + 3][a_row] = na.w;
            *(float4*)&Bs[nxt][b_row][b_col] = nb;
            __syncthreads();
        }
    }

    float alpha = 1.0f;
    if (AMODE) {
        float w0 = attn[0], w1 = attn[1];
        float mx = fmaxf(w0, w1);
        float e0 = expf(w0 - mx), e1 = expf(w1 - mx);
        alpha = ((AMODE == 1) ? e0 : e1) / (e0 + e1);
    }

#pragma unroll
    for (int i = 0; i < 8; ++i) {
        const int r = m0 + ((i < 4) ? (ry * 4 + i) : (64 + ry * 4 + i - 4));
#pragma unroll
        for (int p = 0; p < 4; ++p) {
            const int c = n0 + ((p < 2) ? (cx * 4 + 2 * p)
                                        : (64 + cx * 4 + 2 * (p - 2)));
            U2 u; u.u = acc[i][p];
            float o0 = alpha * (u.f.x + bias[c]);
            float o1 = alpha * (u.f.y + bias[c + 1]);
            if (RELU) { o0 = fmaxf(o0, 0.0f); o1 = fmaxf(o1, 0.0f); }
            float* Cp = C + (size_t)r * N + c;
            if (ACCUM) { o0 += Cp[0]; o1 += Cp[1]; }
            Cp[0] = o0; Cp[1] = o1;
        }
    }
}

// =================================================================================
// Similarity GEMM via HMMA — R9-PASSING VERSION VERBATIM (fp32-acc 3-term,
// ldmatrix.x4, triangular grid, occupancy 2). Legacy-HMMA pipe-rate bound
// (~31 cyc/SMSP per mma.sync.16816 on sm_100) — frozen.
// =================================================================================
#define SIM_TILE   128
#define SIM_KC     32
#define SIM_NCH    (HIDDIM / SIM_KC)      // 16
#define SIM_TSZ    (128 * 40 * 2)         // 10240 bytes per tile (stride 80B)
#define SIM_BUFSZ  (4 * SIM_TSZ)          // Ahi,Alo,Bhi,Blo = 40960
#define SIM_SMEM   (2 * SIM_BUFSZ)        // 81920
#define SIM_NB     (NNODES / SIM_TILE)    // 64
#define SIM_GRID   (SIM_NB * (SIM_NB + 1) / 2)   // 2080

__device__ __forceinline__ void sim_stage(
    uint32_t sb, int buf, const __half* __restrict__ nh,
    const __half* __restrict__ nl, int m0, int n0, int kc0, int tid)
{
    const uint32_t bo = sb + buf * SIM_BUFSZ;
    for (int task = tid; task < 512; task += 256) {
        const int r = task >> 2, v = task & 3;
        const uint32_t d = bo + (uint32_t)(r * 80 + v * 16);
        const size_t ma = (size_t)(m0 + r) * HIDDIM + kc0 + v * 8;
        const size_t na = (size_t)(n0 + r) * HIDDIM + kc0 + v * 8;
        cpasync16(d,                nh + ma);
        cpasync16(d + SIM_TSZ,      nl + ma);
        cpasync16(d + 2 * SIM_TSZ,  nh + na);
        cpasync16(d + 3 * SIM_TSZ,  nl + na);
    }
}

__global__ void __launch_bounds__(256, 2) sim_hmma_kernel(
    const __half* __restrict__ nh, const __half* __restrict__ nl,
    float* __restrict__ sim)
{
    // triangular decode: linear block -> (by, bx) with by <= bx
    int L = blockIdx.x;
    int by = 0;
    while (L >= SIM_NB - by) { L -= SIM_NB - by; ++by; }
    const int bx = by + L;

    extern __shared__ __align__(16) char smem[];
    const uint32_t sb = smem_u32(smem);

    const int tid = threadIdx.x;
    const int wid = tid >> 5, lane = tid & 31;
    const int wr = wid >> 1, wc = wid & 1;       // 4 x 2 warps
    const int g = lane >> 2, t = lane & 3;
    const int m0 = by * SIM_TILE;
    const int n0 = bx * SIM_TILE;

    const int sub = lane >> 3, lr = lane & 7;
    const uint32_t aoff0 =
        (uint32_t)((wr * 32 + (sub & 1) * 8 + lr) * 80 + (sub >> 1) * 16);
    const uint32_t boff0 =
        (uint32_t)((wc * 64 + (sub >> 1) * 8 + lr) * 80 + (sub & 1) * 16);

    float acc[2][8][4];
#pragma unroll
    for (int i = 0; i < 2; ++i)
#pragma unroll
        for (int j = 0; j < 8; ++j)
#pragma unroll
            for (int p = 0; p < 4; ++p) acc[i][j][p] = 0.0f;

    sim_stage(sb, 0, nh, nl, m0, n0, 0, tid);
    CP_COMMIT();
    CP_WAIT0();
    __syncthreads();

    for (int ch = 0; ch < SIM_NCH; ++ch) {
        const int cur = ch & 1;
        if (ch + 1 < SIM_NCH) {
            sim_stage(sb, cur ^ 1, nh, nl, m0, n0, (ch + 1) * SIM_KC, tid);
            CP_COMMIT();
        }

        const uint32_t tb = sb + cur * SIM_BUFSZ;

#pragma unroll
        for (int ks = 0; ks < 2; ++ks) {
            const uint32_t ko = (uint32_t)(ks * 32);
            uint32_t ah[2][4], al[2][4];
            ldmx4(ah[0], tb + aoff0 + ko);
            ldmx4(ah[1], tb + aoff0 + 1280 + ko);
            ldmx4(al[0], tb + SIM_TSZ + aoff0 + ko);
            ldmx4(al[1], tb + SIM_TSZ + aoff0 + 1280 + ko);
#pragma unroll
            for (int jp = 0; jp < 4; ++jp) {
                uint32_t bh[4], bl[4];
                ldmx4(bh, tb + 2 * SIM_TSZ + boff0 + (uint32_t)(jp * 1280) + ko);
                ldmx4(bl, tb + 3 * SIM_TSZ + boff0 + (uint32_t)(jp * 1280) + ko);
                const int j0 = jp * 2, j1 = jp * 2 + 1;
                hmma(acc[0][j0], ah[0], bh[0], bh[1]);
                hmma(acc[1][j0], ah[1], bh[0], bh[1]);
                hmma(acc[0][j1], ah[0], bh[2], bh[3]);
                hmma(acc[1][j1], ah[1], bh[2], bh[3]);
                hmma(acc[0][j0], ah[0], bl[0], bl[1]);
                hmma(acc[1][j0], ah[1], bl[0], bl[1]);
                hmma(acc[0][j1], ah[0], bl[2], bl[3]);
                hmma(acc[1][j1], ah[1], bl[2], bl[3]);
                hmma(acc[0][j0], al[0], bh[0], bh[1]);
                hmma(acc[1][j0], al[1], bh[0], bh[1]);
                hmma(acc[0][j1], al[0], bh[2], bh[3]);
                hmma(acc[1][j1], al[1], bh[2], bh[3]);
            }
        }

        if (ch + 1 < SIM_NCH) {
            CP_WAIT0();
            __syncthreads();
        }
    }

    // ---- epilogue: stage C tile in SMEM (stride 129), write both orientations
    __syncthreads();
    float* Cs = (float*)smem;
#pragma unroll
    for (int i = 0; i < 2; ++i) {
        const int row = wr * 32 + i * 16 + g;
#pragma unroll
        for (int j = 0; j < 8; ++j) {
            const int col = wc * 64 + j * 8 + 2 * t;
            Cs[row * 129 + col]           = acc[i][j][0];
            Cs[row * 129 + col + 1]       = acc[i][j][1];
            Cs[(row + 8) * 129 + col]     = acc[i][j][2];
            Cs[(row + 8) * 129 + col + 1] = acc[i][j][3];
        }
    }
    __syncthreads();

    for (int idx = tid; idx < 128 * 32; idx += 256) {
        const int r = idx >> 5, q = (idx & 31) * 4;
        float4 v;
        v.x = Cs[r * 129 + q];     v.y = Cs[r * 129 + q + 1];
        v.z = Cs[r * 129 + q + 2]; v.w = Cs[r * 129 + q + 3];
        *(float4*)&sim[(size_t)(m0 + r) * NNODES + n0 + q] = v;
    }
    if (bx != by) {
        for (int idx = tid; idx < 128 * 32; idx += 256) {
            const int c = idx >> 5, q = (idx & 31) * 4;
            float4 v;
            v.x = Cs[(q)     * 129 + c]; v.y = Cs[(q + 1) * 129 + c];
            v.z = Cs[(q + 2) * 129 + c]; v.w = Cs[(q + 3) * 129 + c];
            *(float4*)&sim[(size_t)(n0 + c) * NNODES + m0 + q] = v;
        }
    }
}

// =================================================================================
// Row stats: rowmean = mean(fused); normed emitted as hi/lo fp16 split.
// =================================================================================
__global__ void rowstats_kernel(const float* __restrict__ fused,
                                __half* __restrict__ nh,
                                __half* __restrict__ nl,
                                float* __restrict__ rowmean)
{
    const int row = blockIdx.x;
    const int tid = threadIdx.x;
    const float* fp = fused + (size_t)row * HIDDIM;
    float x0 = fp[tid], x1 = fp[tid + 256];
    float s = x0 + x1;
    float q = x0 * x0 + x1 * x1;
#pragma unroll
    for (int o = 16; o; o >>= 1) {
        s += __shfl_xor_sync(0xffffffffu, s, o);
        q += __shfl_xor_sync(0xffffffffu, q, o);
    }
    __shared__ float ss[8], qq[8];
    __shared__ float s_den;
    if ((tid & 31) == 0) { ss[tid >> 5] = s; qq[tid >> 5] = q; }
    __syncthreads();
    if (tid == 0) {
        float S = 0.0f, Q = 0.0f;
#pragma unroll
        for (int i = 0; i < 8; ++i) { S += ss[i]; Q += qq[i]; }
        s_den = fmaxf(sqrtf(Q), 1e-12f);
        rowmean[row] = S * (1.0f / HIDDIM);
    }
    __syncthreads();
    const float den = s_den;
    const size_t base = (size_t)row * HIDDIM;
    float v0 = x0 / den, v1 = x1 / den;
    __half h0v = __float2half_rn(v0);
    __half h1v = __float2half_rn(v1);
    nh[base + tid]       = h0v;
    nh[base + tid + 256] = h1v;
    nl[base + tid]       = __float2half_rn(v0 - __half2float(h0v));
    nl[base + tid + 256] = __float2half_rn(v1 - __half2float(h1v));
}

// =================================================================================
// Per-row top-17. Scan + insert: R9 verbatim. Merge: same decision function
// (max value, tie -> min index; advance the winning thread's head) but via a
// warp-shuffle tournament -> 2 block barriers/round instead of ~11.
// =================================================================================
__device__ __forceinline__ void topk_insert_r5(float v, int j, float* lv, int* li)
{
    if (v > lv[TKK - 1]) {
        int t = TKK - 1;
        while (t > 0 && lv[t - 1] < v) {
            lv[t] = lv[t - 1]; li[t] = li[t - 1]; --t;
        }
        lv[t] = v; li[t] = j;
    }
}

__global__ void topk_kernel(const float* __restrict__ sim,
                            const float* __restrict__ rowmean,
                            int* __restrict__ nbrs,
                            float* __restrict__ wout,
                            int* __restrict__ keep)
{
    const int row = blockIdx.x;
    const int tid = threadIdx.x;
    const int lane = tid & 31, warp = tid >> 5;
    const float4* sp4 = (const float4*)(sim + (size_t)row * NNODES);

    float lv[TKK]; int li[TKK];
#pragma unroll
    for (int t = 0; t < TKK; ++t) { lv[t] = -3.4e38f; li[t] = 0x7fffffff; }

#pragma unroll 1
    for (int it = 0; it < 8; ++it) {
        const int vidx = tid + it * 256;
        float4 v4 = sp4[vidx];
        const int jb = vidx * 4;
        topk_insert_r5(v4.x, jb,     lv, li);
        topk_insert_r5(v4.y, jb + 1, lv, li);
        topk_insert_r5(v4.z, jb + 2, lv, li);
        topk_insert_r5(v4.w, jb + 3, lv, li);
    }

    __shared__ float wvs[8];
    __shared__ int   wis[8];
    __shared__ int   wos[8];
    __shared__ int   sel[TKK];
    __shared__ int   s_owner;

    int head = 0;
    for (int round = 0; round < TKK; ++round) {
        float v = (head < TKK) ? lv[head] : -3.4e38f;
        int   i = (head < TKK) ? li[head] : 0x7fffffff;
        int   o = tid;
        // warp-local tournament (no barriers)
#pragma unroll
        for (int s = 16; s; s >>= 1) {
            float v2 = __shfl_down_sync(0xffffffffu, v, s);
            int   i2 = __shfl_down_sync(0xffffffffu, i, s);
            int   o2 = __shfl_down_sync(0xffffffffu, o, s);
            if (v2 > v || (v2 == v && i2 < i)) { v = v2; i = i2; o = o2; }
        }
        if (lane == 0) { wvs[warp] = v; wis[warp] = i; wos[warp] = o; }
        __syncthreads();
        if (warp == 0) {
            float v3 = (lane < 8) ? wvs[lane] : -3.4e38f;
            int   i3 = (lane < 8) ? wis[lane] : 0x7fffffff;
            int   o3 = (lane < 8) ? wos[lane] : 0;
#pragma unroll
            for (int s = 4; s; s >>= 1) {
                float v2 = __shfl_down_sync(0xffffffffu, v3, s);
                int   i2 = __shfl_down_sync(0xffffffffu, i3, s);
                int   o2 = __shfl_down_sync(0xffffffffu, o3, s);
                if (v2 > v3 || (v2 == v3 && i2 < i3)) { v3 = v2; i3 = i2; o3 = o2; }
            }
            if (lane == 0) { sel[round] = i3; s_owner = o3; }
        }
        __syncthreads();
        if (tid == s_owner) ++head;
        // no barrier needed: s_owner for the next round is written only after
        // the next round's first __syncthreads(), by which time every thread
        // has consumed this round's value.
    }

    if (tid == 0) {
        int nb[KTOP]; int c = 0;
        for (int t = 0; t < TKK; ++t)
            if (sel[t] != row && c < KTOP) nb[c++] = sel[t];
        float s = rowmean[row];
#pragma unroll
        for (int t = 0; t < KTOP; ++t) {
            s += rowmean[nb[t]];
            nbrs[row * KTOP + t] = nb[t];
        }
        float mean = s * (1.0f / (float)TKK);
        wout[row] = 1.0f / (1.0f + expf(-mean));
        keep[row] = (mean > 0.0f) ? 1 : 0;
    }
}

// ---------------- output zero + scatter ----------------
__global__ void zero_kernel(float* __restrict__ p, long long n)
{
    long long n4 = n >> 2;
    float4* p4 = (float4*)p;
    long long i = (long long)blockIdx.x * blockDim.x + threadIdx.x;
    long long stride = (long long)gridDim.x * blockDim.x;
    float4 z = make_float4(0.f, 0.f, 0.f, 0.f);
    for (; i < n4; i += stride) p4[i] = z;
    if (blockIdx.x == 0 && threadIdx.x == 0)
        for (long long t = n4 << 2; t < n; ++t) p[t] = 0.f;
}

__global__ void scatter_kernel(const int* __restrict__ nbrs,
                               const float* __restrict__ w,
                               const int* __restrict__ keep,
                               float* __restrict__ out)
{
    const int i = blockIdx.x * blockDim.x + threadIdx.x;
    if (i >= NNODES) return;
    const int kp = keep[i];
    out[(size_t)NNODES * NNODES + i] = kp ? w[i] : 0.0f;
    if (kp) {
        out[(size_t)i * NNODES + i] = 1.0f;
#pragma unroll
        for (int t = 0; t < KTOP; ++t) {
            int n = nbrs[i * KTOP + t];
            out[(size_t)n * NNODES + i] = 1.0f;
        }
    }
}

// =================================================================================
extern "C" void kernel_launch(void* const* d_in, const int* in_sizes, int n_in,
                              void* d_out, int out_size)
{
    const float* x0   = (const float*)d_in[0];
    const float* x1   = (const float*)d_in[1];
    const float* w1_0 = (const float*)d_in[2];
    const float* b1_0 = (const float*)d_in[3];
    const float* w2_0 = (const float*)d_in[4];
    const float* b2_0 = (const float*)d_in[5];
    const float* w1_1 = (const float*)d_in[6];
    const float* b1_1 = (const float*)d_in[7];
    const float* w2_1 = (const float*)d_in[8];
    const float* b2_1 = (const float*)d_in[9];
    const float* attn = (const float*)d_in[10];
    const float* fw   = (const float*)d_in[11];
    const float* fb   = (const float*)d_in[12];
    float* out = (float*)d_out;

    float *h0, *h1, *f, *fused, *rowmean, *sim, *wv;
    __half *nh, *nl;
    int *nbrs, *keep;
    cudaGetSymbolAddress((void**)&h0, g_h0);
    cudaGetSymbolAddress((void**)&h1, g_h1);
    cudaGetSymbolAddress((void**)&f, g_f);
    cudaGetSymbolAddress((void**)&fused, g_fused);
    cudaGetSymbolAddress((void**)&nh, g_nh);
    cudaGetSymbolAddress((void**)&nl, g_nl);
    cudaGetSymbolAddress((void**)&rowmean, g_rowmean);
    cudaGetSymbolAddress((void**)&sim, g_sim);
    cudaGetSymbolAddress((void**)&nbrs, g_nbrs);
    cudaGetSymbolAddress((void**)&wv, g_w);
    cudaGetSymbolAddress((void**)&keep, g_keep);

    cudaFuncSetAttribute(sim_hmma_kernel,
                         cudaFuncAttributeMaxDynamicSharedMemorySize, SIM_SMEM);

    const long long total_out = (long long)NNODES * NNODES + NNODES;
    zero_kernel<<<4096, 256>>>(out, total_out);

    dim3 blk(256);
    // layer 1 (ReLU)
    gemm_nn<1, 0, 0><<<dim3(HIDDIM / 128, NNODES / 128), blk>>>(
        x0, w1_0, b1_0, nullptr, h0, NNODES, HIDDIM, 512);
    gemm_nn<1, 0, 0><<<dim3(HIDDIM / 128, NNODES / 128), blk>>>(
        x1, w1_1, b1_1, nullptr, h1, NNODES, HIDDIM, 768);
    // layer 2 scaled by softmax(attn): f = a0*(h0@w2_0+b2_0) + a1*(h1@w2_1+b2_1)
    gemm_nn<0, 1, 0><<<dim3(HIDDIM / 128, NNODES / 128), blk>>>(
        h0, w2_0, b2_0, attn, f, NNODES, HIDDIM, HIDDIM);
    gemm_nn<0, 2, 1><<<dim3(HIDDIM / 128, NNODES / 128), blk>>>(
        h1, w2_1, b2_1, attn, f, NNODES, HIDDIM, HIDDIM);
    // fusion
    gemm_nn<0, 0, 0><<<dim3(HIDDIM / 128, NNODES / 128), blk>>>(
        f, fw, fb, nullptr, fused, NNODES, HIDDIM, HIDDIM);

    rowstats_kernel<<<NNODES, 256>>>(fused, nh, nl, rowmean);

    sim_hmma_kernel<<<SIM_GRID, blk, SIM_SMEM>>>(nh, nl, sim);

    topk_kernel<<<NNODES, 256>>>(sim, rowmean, nbrs, wv, keep);

    scatter_kernel<<<(NNODES + 255) / 256, 256>>>(nbrs, wv, keep, out);
}